// round 7
// baseline (speedup 1.0000x reference)
#include <cuda_runtime.h>
#include <cuda_bf16.h>
#include <stdint.h>
#include <math.h>

#define BB   16384
#define HH   256
#define OUTF 256
#define LL   7
#define G4   1024
#define KT   512

// ---------------- scratch (__device__ globals; no allocs allowed) ----------------
__device__ __align__(256) __nv_bfloat16  g_ahi[(size_t)BB * KT];              // activations hi [B,512]
__device__ __align__(256) __nv_bfloat16  g_alo[(size_t)BB * KT];              // activations lo
__device__ __align__(256) __nv_bfloat16  g_whi[(size_t)(LL + 1) * G4 * KT];   // weights hi [8][1024][512] (gate-reordered)
__device__ __align__(256) __nv_bfloat16  g_wlo[(size_t)(LL + 1) * G4 * KT];
__device__ __align__(256) __nv_bfloat16  g_wouthi[HH * HH];
__device__ __align__(256) __nv_bfloat16  g_woutlo[HH * HH];
__device__ __align__(256) float          g_bias[(LL + 1) * G4];               // combined (bi+bh), gate-reordered

// ---------------- PTX helpers (arch-portable, sm_80/90 baseline) ----------------
__device__ __forceinline__ uint32_t smem_u32(const void* p) {
    uint32_t a;
    asm("{ .reg .u64 t; cvta.to.shared.u64 t, %1; cvt.u32.u64 %0, t; }" : "=r"(a) : "l"(p));
    return a;
}
__device__ __forceinline__ void cp16(uint32_t s, const void* g) {
    asm volatile("cp.async.cg.shared.global [%0], [%1], 16;" :: "r"(s), "l"(g));
}
__device__ __forceinline__ void ldmatrix_x4(uint32_t r[4], uint32_t addr) {
    asm volatile("ldmatrix.sync.aligned.m8n8.x4.shared.b16 {%0,%1,%2,%3}, [%4];"
        : "=r"(r[0]), "=r"(r[1]), "=r"(r[2]), "=r"(r[3]) : "r"(addr));
}
__device__ __forceinline__ void mma16816(float c[4], const uint32_t a[4],
                                         uint32_t b0, uint32_t b1) {
    asm volatile("mma.sync.aligned.m16n8k16.row.col.f32.bf16.bf16.f32 "
        "{%0,%1,%2,%3}, {%4,%5,%6,%7}, {%8,%9}, {%0,%1,%2,%3};"
        : "+f"(c[0]), "+f"(c[1]), "+f"(c[2]), "+f"(c[3])
        : "r"(a[0]), "r"(a[1]), "r"(a[2]), "r"(a[3]), "r"(b0), "r"(b1));
}
__device__ __forceinline__ float sigf(float x) { return 1.0f / (1.0f + __expf(-x)); }

// ---------------- split-bf16 TN GEMM via mma.sync (HMMA), 3-stage cp.async ----------------
// C[m,n] = sum_k (Ahi+Alo)[m,k]*(Bhi+Blo)[n,k]  (3 passes: hi*hi, lo*hi, hi*lo)
#define TM 256
#define TN 128
#define NTHREADS 512
#define STAGE_A (TM * 128)                 // 32 KB
#define STAGE_B (TN * 128)                 // 16 KB
#define STAGE   (STAGE_A + STAGE_B)        // 48 KB
#define NSTAGE  3
#define SMEMSZ  (NSTAGE * STAGE)           // 144 KB

// FUSED: weights gate-reordered (n = (unit/8)*32 + gate*8 + unit%8); epilogue applies
// LSTM gating and writes h (fp32), c (fp32), and bf16 hi/lo splits of h.
template<bool FUSED>
__global__ void __launch_bounds__(NTHREADS, 1) mma_gemm(
    const __nv_bfloat16* __restrict__ Ahi, const __nv_bfloat16* __restrict__ Alo, int sA,
    const __nv_bfloat16* __restrict__ Bhi, const __nv_bfloat16* __restrict__ Blo, int sB,
    int Ktot, const float* __restrict__ bias,
    float* __restrict__ C, int sC,
    const float* __restrict__ c_in, float* __restrict__ h_out, float* __restrict__ c_out,
    __nv_bfloat16* __restrict__ oahi, __nv_bfloat16* __restrict__ oalo)
{
    extern __shared__ __align__(128) char dsm[];
    const int tid  = threadIdx.x;
    const int lane = tid & 31;
    const int wid  = tid >> 5;
    const int wm   = wid & 3;        // 4 warps along M (64 each)
    const int wn   = wid >> 2;       // 4 warps along N (32 each)
    const int m0   = blockIdx.y * TM;
    const int n0   = blockIdx.x * TN;
    const uint32_t sbase = smem_u32(dsm);

    const int nchunks = Ktot >> 6;   // BK = 64
    const int niter   = 3 * nchunks;

    float c[4][4][4];
    #pragma unroll
    for (int i = 0; i < 4; ++i)
        #pragma unroll
        for (int j = 0; j < 4; ++j)
            #pragma unroll
            for (int q = 0; q < 4; ++q) c[i][j][q] = 0.0f;

    auto load_stage = [&](int buf, int iter) {
        const int p  = iter / nchunks;
        const int kc = (iter - p * nchunks) << 6;
        const __nv_bfloat16* Ap = (p == 1) ? Alo : Ahi;
        const __nv_bfloat16* Bp = (p == 2) ? Blo : Bhi;
        const uint32_t sa = sbase + buf * STAGE;
        const uint32_t sb = sa + STAGE_A;
        #pragma unroll
        for (int i = 0; i < 4; ++i) {                    // A: 256 rows x 8 chunks of 16B
            int idx = tid + i * NTHREADS;
            int row = idx >> 3, kg = idx & 7;
            cp16(sa + row * 128 + (((kg ^ (row & 7))) << 4),
                 Ap + (size_t)(m0 + row) * sA + kc + kg * 8);
        }
        #pragma unroll
        for (int i = 0; i < 2; ++i) {                    // B: 128 rows x 8 chunks
            int idx = tid + i * NTHREADS;
            int row = idx >> 3, kg = idx & 7;
            cp16(sb + row * 128 + (((kg ^ (row & 7))) << 4),
                 Bp + (size_t)(n0 + row) * sB + kc + kg * 8);
        }
        asm volatile("cp.async.commit_group;");
    };

    load_stage(0, 0);
    load_stage(1, 1);

    int buf = 0;
    #pragma unroll 1
    for (int i = 0; i < niter; ++i) {
        if (i + 2 < niter) {
            load_stage((buf + 2) % NSTAGE, i + 2);
            asm volatile("cp.async.wait_group 2;");
        } else if (i + 1 < niter) {
            asm volatile("cp.async.commit_group;");
            asm volatile("cp.async.wait_group 2;");
        } else {
            asm volatile("cp.async.wait_group 0;");
        }
        __syncthreads();

        const uint32_t sa = sbase + buf * STAGE;
        const uint32_t sb = sa + STAGE_A;
        const int tile = lane >> 3;
        const int lr   = lane & 7;

        #pragma unroll
        for (int ks = 0; ks < 4; ++ks) {                 // 4 k16 steps per BK=64
            uint32_t a[4][4];
            #pragma unroll
            for (int mi = 0; mi < 4; ++mi) {
                int row = wm * 64 + mi * 16 + ((tile & 1) << 3) + lr;
                int kg  = 2 * ks + (tile >> 1);
                ldmatrix_x4(a[mi], sa + row * 128 + ((kg ^ (row & 7)) << 4));
            }
            uint32_t b[2][4];
            #pragma unroll
            for (int nj = 0; nj < 2; ++nj) {
                int row = wn * 32 + nj * 16 + ((tile >> 1) << 3) + lr;
                int kg  = 2 * ks + (tile & 1);
                ldmatrix_x4(b[nj], sb + row * 128 + ((kg ^ (row & 7)) << 4));
            }
            #pragma unroll
            for (int mi = 0; mi < 4; ++mi)
                #pragma unroll
                for (int nj = 0; nj < 2; ++nj) {
                    mma16816(c[mi][nj * 2 + 0], a[mi], b[nj][0], b[nj][1]);
                    mma16816(c[mi][nj * 2 + 1], a[mi], b[nj][2], b[nj][3]);
                }
        }
        __syncthreads();
        buf = (buf + 1 == NSTAGE) ? 0 : buf + 1;
    }

    if (!FUSED) {
        // plain epilogue: bias add, fp32 store
        #pragma unroll
        for (int mi = 0; mi < 4; ++mi) {
            const int r0 = m0 + wm * 64 + mi * 16 + (lane >> 2);
            #pragma unroll
            for (int n8 = 0; n8 < 4; ++n8) {
                const int col = n0 + wn * 32 + n8 * 8 + ((lane & 3) << 1);
                float bx = 0.0f, by = 0.0f;
                if (bias) { bx = bias[col]; by = bias[col + 1]; }
                *(float2*)&C[(size_t)r0 * sC + col] =
                    make_float2(c[mi][n8][0] + bx, c[mi][n8][1] + by);
                *(float2*)&C[(size_t)(r0 + 8) * sC + col] =
                    make_float2(c[mi][n8][2] + bx, c[mi][n8][3] + by);
            }
        }
    } else {
        // fused LSTM epilogue. Columns are gate-reordered: within each 32-col warp
        // tile, col = gate*8 + unit_local; each thread's 4 col-groups = the 4 gates
        // of units (lane&3)*2 and +1.
        const int ub = ((n0 + wn * 32) >> 2) + ((lane & 3) << 1);   // global unit for e=0
        float bsv[4][2];
        #pragma unroll
        for (int g = 0; g < 4; ++g) {
            bsv[g][0] = bias[n0 + wn * 32 + g * 8 + ((lane & 3) << 1)];
            bsv[g][1] = bias[n0 + wn * 32 + g * 8 + ((lane & 3) << 1) + 1];
        }
        #pragma unroll
        for (int mi = 0; mi < 4; ++mi) {
            #pragma unroll
            for (int rh = 0; rh < 2; ++rh) {
                const int row = m0 + wm * 64 + mi * 16 + rh * 8 + (lane >> 2);
                const float2 cin = *(const float2*)&c_in[(size_t)row * HH + ub];
                float hv[2], cv[2];
                #pragma unroll
                for (int e = 0; e < 2; ++e) {
                    const int q = rh * 2 + e;
                    float gi = sigf (c[mi][0][q] + bsv[0][e]);
                    float gf = sigf (c[mi][1][q] + bsv[1][e]);
                    float gg = tanhf(c[mi][2][q] + bsv[2][e]);
                    float go = sigf (c[mi][3][q] + bsv[3][e]);
                    float ci = e ? cin.y : cin.x;
                    cv[e] = gf * ci + gi * gg;
                    hv[e] = go * tanhf(cv[e]);
                }
                *(float2*)&c_out[(size_t)row * HH + ub] = make_float2(cv[0], cv[1]);
                *(float2*)&h_out[(size_t)row * HH + ub] = make_float2(hv[0], hv[1]);
                __nv_bfloat16 h0 = __float2bfloat16(hv[0]);
                __nv_bfloat16 h1 = __float2bfloat16(hv[1]);
                __nv_bfloat16 l0 = __float2bfloat16(hv[0] - __bfloat162float(h0));
                __nv_bfloat16 l1 = __float2bfloat16(hv[1] - __bfloat162float(h1));
                *(__nv_bfloat162*)&oahi[(size_t)row * KT + ub] = __nv_bfloat162(h0, h1);
                *(__nv_bfloat162*)&oalo[(size_t)row * KT + ub] = __nv_bfloat162(l0, l1);
            }
        }
    }
}

// ---------------- conversion kernels ----------------
__device__ __forceinline__ void split_store4(float4 v, __nv_bfloat16* hi, __nv_bfloat16* lo) {
    __nv_bfloat16 h0 = __float2bfloat16(v.x), h1 = __float2bfloat16(v.y);
    __nv_bfloat16 h2 = __float2bfloat16(v.z), h3 = __float2bfloat16(v.w);
    __nv_bfloat16 l0 = __float2bfloat16(v.x - __bfloat162float(h0));
    __nv_bfloat16 l1 = __float2bfloat16(v.y - __bfloat162float(h1));
    __nv_bfloat16 l2 = __float2bfloat16(v.z - __bfloat162float(h2));
    __nv_bfloat16 l3 = __float2bfloat16(v.w - __bfloat162float(h3));
    ((__nv_bfloat162*)hi)[0] = __nv_bfloat162(h0, h1);
    ((__nv_bfloat162*)hi)[1] = __nv_bfloat162(h2, h3);
    ((__nv_bfloat162*)lo)[0] = __nv_bfloat162(l0, l1);
    ((__nv_bfloat162*)lo)[1] = __nv_bfloat162(l2, l3);
}

// x [B,256] -> act hi/lo cols 0-255
__global__ void __launch_bounds__(256) conv_x(const float* __restrict__ x) {
    int t = blockIdx.x * blockDim.x + threadIdx.x;
    int b = t >> 6, c4 = (t & 63) << 2;
    float4 v = *(const float4*)(x + (size_t)b * HH + c4);
    split_store4(v, &g_ahi[(size_t)b * KT + c4], &g_alo[(size_t)b * KT + c4]);
}

// h_all[l] [B,256] -> act hi/lo cols 256-511
__global__ void __launch_bounds__(256) conv_h(const float* __restrict__ hsrc) {
    int t = blockIdx.x * blockDim.x + threadIdx.x;
    int b = t >> 6, c4 = (t & 63) << 2;
    float4 v = *(const float4*)(hsrc + (size_t)b * HH + c4);
    split_store4(v, &g_ahi[(size_t)b * KT + 256 + c4], &g_alo[(size_t)b * KT + 256 + c4]);
}

// weights: dest row nn is gate-reordered; [Wih_l | Whh_l] concat along K, split hi/lo
__global__ void __launch_bounds__(256) conv_w(
    const float* __restrict__ Wih0, const float* __restrict__ Whh0,
    const float* __restrict__ Wih,  const float* __restrict__ Whh)
{
    int t  = blockIdx.x * blockDim.x + threadIdx.x;     // 1048576
    int k4 = (t & 127) << 2;
    int nn = (t >> 7) & 1023;                            // dest (reordered) row
    int l  = t >> 17;
    int gate = (nn >> 3) & 3;
    int unit = ((nn >> 5) << 3) + (nn & 7);
    int no   = gate * 256 + unit;                        // source row
    const float* src;
    if (l == 0) src = (k4 < 256) ? (Wih0 + (size_t)no * 256 + k4)
                                 : (Whh0 + (size_t)no * 256 + (k4 - 256));
    else        src = (k4 < 256) ? (Wih + ((size_t)(l - 1) * G4 + no) * 256 + k4)
                                 : (Whh + ((size_t)(l - 1) * G4 + no) * 256 + (k4 - 256));
    float4 v = *(const float4*)src;
    size_t d = ((size_t)l * G4 + nn) * KT + k4;
    split_store4(v, &g_whi[d], &g_wlo[d]);
}

__global__ void __launch_bounds__(256) conv_wout(const float* __restrict__ Wout) {
    int t = blockIdx.x * blockDim.x + threadIdx.x;      // 16384
    int n = t >> 6, k4 = (t & 63) << 2;
    float4 v = *(const float4*)(Wout + (size_t)n * HH + k4);
    split_store4(v, &g_wouthi[(size_t)n * HH + k4], &g_woutlo[(size_t)n * HH + k4]);
}

// combined biases, gate-reordered: g_bias[l][nn] = bi[no] + bh[no]
__global__ void __launch_bounds__(256) conv_bias(
    const float* __restrict__ bih0, const float* __restrict__ bhh0,
    const float* __restrict__ bih,  const float* __restrict__ bhh)
{
    int t  = blockIdx.x * blockDim.x + threadIdx.x;     // 8192
    int nn = t & 1023;
    int l  = t >> 10;
    int gate = (nn >> 3) & 3;
    int unit = ((nn >> 5) << 3) + (nn & 7);
    int no   = gate * 256 + unit;
    float v;
    if (l == 0) v = bih0[no] + bhh0[no];
    else        v = bih[(size_t)(l - 1) * G4 + no] + bhh[(size_t)(l - 1) * G4 + no];
    g_bias[t] = v;
}

// ---------------- launch ----------------
extern "C" void kernel_launch(void* const* d_in, const int* in_sizes, int n_in,
                              void* d_out, int out_size)
{
    const float* x     = (const float*)d_in[0];
    const float* h_all = (const float*)d_in[1];
    const float* c_all = (const float*)d_in[2];
    const float* Wih0  = (const float*)d_in[3];
    const float* Whh0  = (const float*)d_in[4];
    const float* bih0  = (const float*)d_in[5];
    const float* bhh0  = (const float*)d_in[6];
    const float* Wih   = (const float*)d_in[7];
    const float* Whh   = (const float*)d_in[8];
    const float* bih   = (const float*)d_in[9];
    const float* bhh   = (const float*)d_in[10];
    const float* Wout  = (const float*)d_in[11];
    const float* bout  = (const float*)d_in[12];

    float* out = (float*)d_out;
    float* hs  = out + (size_t)BB * OUTF;
    float* cs  = hs + (size_t)(LL + 1) * BB * HH;

    __nv_bfloat16 *ahi, *alo, *whi, *wlo, *wouthi, *woutlo; float* biasc;
    cudaGetSymbolAddress((void**)&ahi,    g_ahi);
    cudaGetSymbolAddress((void**)&alo,    g_alo);
    cudaGetSymbolAddress((void**)&whi,    g_whi);
    cudaGetSymbolAddress((void**)&wlo,    g_wlo);
    cudaGetSymbolAddress((void**)&wouthi, g_wouthi);
    cudaGetSymbolAddress((void**)&woutlo, g_woutlo);
    cudaGetSymbolAddress((void**)&biasc,  g_bias);

    cudaFuncSetAttribute(mma_gemm<true>,  cudaFuncAttributeMaxDynamicSharedMemorySize, SMEMSZ);
    cudaFuncSetAttribute(mma_gemm<false>, cudaFuncAttributeMaxDynamicSharedMemorySize, SMEMSZ);

    const int eb = (BB * HH / 4) / 256;

    conv_w<<<(8 * G4 * KT / 4) / 256, 256>>>(Wih0, Whh0, Wih, Whh);
    conv_wout<<<(HH * HH / 4) / 256, 256>>>(Wout);
    conv_bias<<<32, 256>>>(bih0, bhh0, bih, bhh);
    conv_x<<<eb, 256>>>(x);

    for (int l = 0; l <= LL; ++l) {
        conv_h<<<eb, 256>>>(h_all + (size_t)l * BB * HH);
        mma_gemm<true><<<dim3(G4 / TN, BB / TM), NTHREADS, SMEMSZ>>>(
            ahi, alo, KT,
            whi + (size_t)l * G4 * KT, wlo + (size_t)l * G4 * KT, KT,
            KT, biasc + (size_t)l * G4,
            nullptr, 0,
            c_all + (size_t)l * BB * HH,
            hs + (size_t)l * BB * HH, cs + (size_t)l * BB * HH,
            ahi, alo);
    }

    // output = h_last @ Wout.T + bout   (h_last hi/lo live in act cols 0-255)
    mma_gemm<false><<<dim3(OUTF / TN, BB / TM), NTHREADS, SMEMSZ>>>(
        ahi, alo, KT, wouthi, woutlo, HH,
        HH, bout, out, OUTF,
        nullptr, nullptr, nullptr, nullptr, nullptr);
}

// round 11
// speedup vs baseline: 1.1011x; 1.1011x over previous
#include <cuda_runtime.h>
#include <stdint.h>
#include <math.h>

#define BB   16384
#define HH   256
#define OUTF 256
#define LL   7
#define G4   1024
#define KT   512

// ---------------- scratch (__device__ globals; no allocs allowed) ----------------
__device__ __align__(256) float g_w[(size_t)(LL + 1) * G4 * KT];   // [8][1024][512] tf32-rounded, gate-reordered, [Wih|Whh] K-concat
__device__ __align__(256) float g_wout[OUTF * HH];                 // tf32-rounded
__device__ __align__(256) float g_bias[(LL + 1) * G4];             // combined (bi+bh), gate-reordered

// ---------------- PTX helpers (arch-portable, sm_80+ baseline) ----------------
__device__ __forceinline__ uint32_t smem_u32(const void* p) {
    uint32_t a;
    asm("{ .reg .u64 t; cvta.to.shared.u64 t, %1; cvt.u32.u64 %0, t; }" : "=r"(a) : "l"(p));
    return a;
}
__device__ __forceinline__ void cp16(uint32_t s, const void* g) {
    asm volatile("cp.async.cg.shared.global [%0], [%1], 16;" :: "r"(s), "l"(g));
}
__device__ __forceinline__ uint32_t lds_f32_tf32(uint32_t addr) {
    float f; asm volatile("ld.shared.f32 %0, [%1];" : "=f"(f) : "r"(addr));
    uint32_t u; asm volatile("cvt.rna.tf32.f32 %0, %1;" : "=r"(u) : "f"(f));
    return u;
}
__device__ __forceinline__ uint32_t lds_u32(uint32_t addr) {
    uint32_t u; asm volatile("ld.shared.b32 %0, [%1];" : "=r"(u) : "r"(addr));
    return u;
}
__device__ __forceinline__ void mma1688(float c[4], const uint32_t a[4],
                                        uint32_t b0, uint32_t b1) {
    asm volatile("mma.sync.aligned.m16n8k8.row.col.f32.tf32.tf32.f32 "
        "{%0,%1,%2,%3}, {%4,%5,%6,%7}, {%8,%9}, {%0,%1,%2,%3};"
        : "+f"(c[0]), "+f"(c[1]), "+f"(c[2]), "+f"(c[3])
        : "r"(a[0]), "r"(a[1]), "r"(a[2]), "r"(a[3]), "r"(b0), "r"(b1));
}
__device__ __forceinline__ float rna_tf32(float x) {
    uint32_t u; asm("cvt.rna.tf32.f32 %0, %1;" : "=r"(u) : "f"(x));
    return __uint_as_float(u);
}
__device__ __forceinline__ float sigf(float x) {
    return __fdividef(1.0f, 1.0f + __expf(-x));
}
__device__ __forceinline__ float tanhfast(float x) {
    return __fdividef(2.0f, 1.0f + __expf(-2.0f * x)) - 1.0f;
}

// ---------------- tf32 TN GEMM via mma.sync, 3-stage cp.async, fused LSTM epilogue ----------------
// C[m,n] = sum_k A[m,k]*W[n,k] (+bias). A = [A1 | A2] along K (each [B,256] fp32).
// Tile 128x128, BK=32 (128B fp32 rows, chunk-XOR swizzle), 256 threads (8 warps: 2 M x 4 N).
#define TM 128
#define TN 128
#define NTHREADS 256
#define STAGE_A (TM * 128)                 // 16 KB
#define STAGE_B (TN * 128)                 // 16 KB
#define STAGE   (STAGE_A + STAGE_B)        // 32 KB
#define NSTAGE  3
#define SMEMSZ  (NSTAGE * STAGE)           // 96 KB -> 2 CTAs/SM

template<bool FUSED>
__global__ void __launch_bounds__(NTHREADS, 2) mma_gemm(
    const float* __restrict__ A1, const float* __restrict__ A2,
    const float* __restrict__ B, int sB, int Ktot,
    const float* __restrict__ bias,
    float* __restrict__ C, int sC,
    const float* __restrict__ c_in, float* __restrict__ h_out, float* __restrict__ c_out)
{
    extern __shared__ __align__(128) char dsm[];
    const int tid  = threadIdx.x;
    const int lane = tid & 31;
    const int wid  = tid >> 5;
    const int wm   = wid & 1;        // 2 warps along M (64 rows)
    const int wn   = wid >> 1;       // 4 warps along N (32 cols)
    const int m0   = blockIdx.y * TM;
    const int n0   = blockIdx.x * TN;
    const uint32_t sbase = smem_u32(dsm);

    const int niter = Ktot >> 5;     // BK = 32

    float c[4][4][4];
    #pragma unroll
    for (int i = 0; i < 4; ++i)
        #pragma unroll
        for (int j = 0; j < 4; ++j)
            #pragma unroll
            for (int q = 0; q < 4; ++q) c[i][j][q] = 0.0f;

    auto load_stage = [&](int buf, int it) {
        const int kc = it << 5;
        const uint32_t sa = sbase + buf * STAGE;
        const uint32_t sb = sa + STAGE_A;
        const float* Asrc; int koff;
        if (kc < 256) { Asrc = A1; koff = kc; } else { Asrc = A2; koff = kc - 256; }
        #pragma unroll
        for (int i = 0; i < 4; ++i) {                    // A: 128 rows x 8 chunks of 16B
            int idx = tid + i * NTHREADS;
            int row = idx >> 3, kg = idx & 7;
            cp16(sa + row * 128 + ((kg ^ (row & 7)) << 4),
                 Asrc + (size_t)(m0 + row) * 256 + koff + kg * 4);
        }
        #pragma unroll
        for (int i = 0; i < 4; ++i) {                    // B: 128 rows x 8 chunks
            int idx = tid + i * NTHREADS;
            int row = idx >> 3, kg = idx & 7;
            cp16(sb + row * 128 + ((kg ^ (row & 7)) << 4),
                 B + (size_t)(n0 + row) * sB + kc + kg * 4);
        }
        asm volatile("cp.async.commit_group;");
    };

    load_stage(0, 0);
    load_stage(1, 1);

    const int lr = lane >> 2;   // 0..7
    const int lc = lane & 3;    // k-low

    int buf = 0;
    #pragma unroll 1
    for (int i = 0; i < niter; ++i) {
        if (i + 2 < niter) {
            load_stage((buf + 2) % NSTAGE, i + 2);
            asm volatile("cp.async.wait_group 2;");
        } else {
            asm volatile("cp.async.wait_group 0;");
        }
        __syncthreads();

        const uint32_t sa = sbase + buf * STAGE;
        const uint32_t sb = sa + STAGE_A;

        #pragma unroll
        for (int ks = 0; ks < 4; ++ks) {                 // 4 k8 steps per BK=32
            const int ch0 = ks * 2, ch1 = ks * 2 + 1;
            uint32_t a[4][4];
            #pragma unroll
            for (int mi = 0; mi < 4; ++mi) {
                const int r0 = wm * 64 + mi * 16 + lr;
                const int r1 = r0 + 8;
                a[mi][0] = lds_f32_tf32(sa + r0 * 128 + ((ch0 ^ (r0 & 7)) << 4) + lc * 4);
                a[mi][1] = lds_f32_tf32(sa + r1 * 128 + ((ch0 ^ (r1 & 7)) << 4) + lc * 4);
                a[mi][2] = lds_f32_tf32(sa + r0 * 128 + ((ch1 ^ (r0 & 7)) << 4) + lc * 4);
                a[mi][3] = lds_f32_tf32(sa + r1 * 128 + ((ch1 ^ (r1 & 7)) << 4) + lc * 4);
            }
            uint32_t b[4][2];
            #pragma unroll
            for (int nj = 0; nj < 4; ++nj) {
                const int n = wn * 32 + nj * 8 + lr;
                b[nj][0] = lds_u32(sb + n * 128 + ((ch0 ^ (n & 7)) << 4) + lc * 4);
                b[nj][1] = lds_u32(sb + n * 128 + ((ch1 ^ (n & 7)) << 4) + lc * 4);
            }
            #pragma unroll
            for (int mi = 0; mi < 4; ++mi)
                #pragma unroll
                for (int nj = 0; nj < 4; ++nj)
                    mma1688(c[mi][nj], a[mi], b[nj][0], b[nj][1]);
        }
        __syncthreads();
        buf = (buf + 1 == NSTAGE) ? 0 : buf + 1;
    }

    if (!FUSED) {
        #pragma unroll
        for (int mi = 0; mi < 4; ++mi) {
            const int r0 = m0 + wm * 64 + mi * 16 + lr;
            #pragma unroll
            for (int nj = 0; nj < 4; ++nj) {
                const int col = n0 + wn * 32 + nj * 8 + lc * 2;
                float bx = 0.0f, by = 0.0f;
                if (bias) { bx = bias[col]; by = bias[col + 1]; }
                *(float2*)&C[(size_t)r0 * sC + col] =
                    make_float2(c[mi][nj][0] + bx, c[mi][nj][1] + by);
                *(float2*)&C[(size_t)(r0 + 8) * sC + col] =
                    make_float2(c[mi][nj][2] + bx, c[mi][nj][3] + by);
            }
        }
    } else {
        // fused LSTM epilogue. Gate-reordered columns: within each 32-col warp tile,
        // col = gate*8 + unit_local; thread's 4 col-groups (nj) = the 4 gates (i,f,g,o)
        // of units (lane&3)*2 and +1.
        const int ub = ((n0 + wn * 32) >> 2) + (lc << 1);   // global unit for e=0
        float bsv[4][2];
        #pragma unroll
        for (int g = 0; g < 4; ++g) {
            bsv[g][0] = bias[n0 + wn * 32 + g * 8 + lc * 2];
            bsv[g][1] = bias[n0 + wn * 32 + g * 8 + lc * 2 + 1];
        }
        #pragma unroll
        for (int mi = 0; mi < 4; ++mi) {
            #pragma unroll
            for (int rh = 0; rh < 2; ++rh) {
                const int row = m0 + wm * 64 + mi * 16 + rh * 8 + lr;
                const float2 cin = *(const float2*)&c_in[(size_t)row * HH + ub];
                float hv[2], cv[2];
                #pragma unroll
                for (int e = 0; e < 2; ++e) {
                    const int q = rh * 2 + e;
                    float gi = sigf    (c[mi][0][q] + bsv[0][e]);
                    float gf = sigf    (c[mi][1][q] + bsv[1][e]);
                    float gg = tanhfast(c[mi][2][q] + bsv[2][e]);
                    float go = sigf    (c[mi][3][q] + bsv[3][e]);
                    float ci = e ? cin.y : cin.x;
                    cv[e] = gf * ci + gi * gg;
                    hv[e] = go * tanhfast(cv[e]);
                }
                *(float2*)&c_out[(size_t)row * HH + ub] = make_float2(cv[0], cv[1]);
                *(float2*)&h_out[(size_t)row * HH + ub] = make_float2(hv[0], hv[1]);
            }
        }
    }
}

// ---------------- weight/bias repack (once per call, fp32, tf32-rounded) ----------------
// dest row nn gate-reordered: nn = (unit/8)*32 + gate*8 + unit%8 ; source no = gate*256 + unit
__global__ void __launch_bounds__(256) conv_w(
    const float* __restrict__ Wih0, const float* __restrict__ Whh0,
    const float* __restrict__ Wih,  const float* __restrict__ Whh)
{
    int t  = blockIdx.x * blockDim.x + threadIdx.x;     // 8*1024*512/4 = 1048576
    int k4 = (t & 127) << 2;
    int nn = (t >> 7) & 1023;
    int l  = t >> 17;
    int gate = (nn >> 3) & 3;
    int unit = ((nn >> 5) << 3) + (nn & 7);
    int no   = gate * 256 + unit;
    const float* src;
    if (l == 0) src = (k4 < 256) ? (Wih0 + (size_t)no * 256 + k4)
                                 : (Whh0 + (size_t)no * 256 + (k4 - 256));
    else        src = (k4 < 256) ? (Wih + ((size_t)(l - 1) * G4 + no) * 256 + k4)
                                 : (Whh + ((size_t)(l - 1) * G4 + no) * 256 + (k4 - 256));
    float4 v = *(const float4*)src;
    v.x = rna_tf32(v.x); v.y = rna_tf32(v.y); v.z = rna_tf32(v.z); v.w = rna_tf32(v.w);
    *(float4*)&g_w[((size_t)l * G4 + nn) * KT + k4] = v;
}

__global__ void __launch_bounds__(256) conv_wout(const float* __restrict__ Wout) {
    int t = blockIdx.x * blockDim.x + threadIdx.x;      // 256*256/4 = 16384
    int n = t >> 6, k4 = (t & 63) << 2;
    float4 v = *(const float4*)(Wout + (size_t)n * HH + k4);
    v.x = rna_tf32(v.x); v.y = rna_tf32(v.y); v.z = rna_tf32(v.z); v.w = rna_tf32(v.w);
    *(float4*)&g_wout[(size_t)n * HH + k4] = v;
}

__global__ void __launch_bounds__(256) conv_bias(
    const float* __restrict__ bih0, const float* __restrict__ bhh0,
    const float* __restrict__ bih,  const float* __restrict__ bhh)
{
    int t  = blockIdx.x * blockDim.x + threadIdx.x;     // 8192
    int nn = t & 1023;
    int l  = t >> 10;
    int gate = (nn >> 3) & 3;
    int unit = ((nn >> 5) << 3) + (nn & 7);
    int no   = gate * 256 + unit;
    float v;
    if (l == 0) v = bih0[no] + bhh0[no];
    else        v = bih[(size_t)(l - 1) * G4 + no] + bhh[(size_t)(l - 1) * G4 + no];
    g_bias[t] = v;
}

// ---------------- launch ----------------
extern "C" void kernel_launch(void* const* d_in, const int* in_sizes, int n_in,
                              void* d_out, int out_size)
{
    const float* x     = (const float*)d_in[0];
    const float* h_all = (const float*)d_in[1];
    const float* c_all = (const float*)d_in[2];
    const float* Wih0  = (const float*)d_in[3];
    const float* Whh0  = (const float*)d_in[4];
    const float* bih0  = (const float*)d_in[5];
    const float* bhh0  = (const float*)d_in[6];
    const float* Wih   = (const float*)d_in[7];
    const float* Whh   = (const float*)d_in[8];
    const float* bih   = (const float*)d_in[9];
    const float* bhh   = (const float*)d_in[10];
    const float* Wout  = (const float*)d_in[11];
    const float* bout  = (const float*)d_in[12];

    float* out = (float*)d_out;
    float* hs  = out + (size_t)BB * OUTF;
    float* cs  = hs + (size_t)(LL + 1) * BB * HH;

    float *w, *wout, *biasc;
    cudaGetSymbolAddress((void**)&w,     g_w);
    cudaGetSymbolAddress((void**)&wout,  g_wout);
    cudaGetSymbolAddress((void**)&biasc, g_bias);

    cudaFuncSetAttribute(mma_gemm<true>,  cudaFuncAttributeMaxDynamicSharedMemorySize, SMEMSZ);
    cudaFuncSetAttribute(mma_gemm<false>, cudaFuncAttributeMaxDynamicSharedMemorySize, SMEMSZ);

    conv_w<<<4096, 256>>>(Wih0, Whh0, Wih, Whh);
    conv_wout<<<64, 256>>>(Wout);
    conv_bias<<<32, 256>>>(bih0, bhh0, bih, bhh);

    for (int l = 0; l <= LL; ++l) {
        const float* a1 = (l == 0) ? x : hs + (size_t)(l - 1) * BB * HH;
        mma_gemm<true><<<dim3(G4 / TN, BB / TM), NTHREADS, SMEMSZ>>>(
            a1, h_all + (size_t)l * BB * HH,
            w + (size_t)l * G4 * KT, KT, KT,
            biasc + (size_t)l * G4,
            nullptr, 0,
            c_all + (size_t)l * BB * HH,
            hs + (size_t)l * BB * HH, cs + (size_t)l * BB * HH);
    }

    // output = h_last @ Wout.T + bout
    mma_gemm<false><<<dim3(OUTF / TN, BB / TM), NTHREADS, SMEMSZ>>>(
        hs + (size_t)LL * BB * HH, nullptr,
        wout, HH, HH,
        bout, out, OUTF,
        nullptr, nullptr, nullptr);
}

// round 13
// speedup vs baseline: 1.5214x; 1.3817x over previous
#include <cuda_runtime.h>
#include <stdint.h>
#include <math.h>

#define BB   16384
#define HH   256
#define OUTF 256
#define LL   7
#define G4   1024
#define KT   512

// ---------------- scratch (__device__ globals; no allocs allowed) ----------------
__device__ __align__(256) float g_w[(size_t)(LL + 1) * G4 * KT];   // tf32-rounded, gate-reordered, [Wih|Whh] K-concat
__device__ __align__(256) float g_wout[OUTF * HH];                 // tf32-rounded
__device__ __align__(256) float g_bias[(LL + 1) * G4];             // combined (bi+bh), gate-reordered
__device__ __align__(256) float g_x_tf[(size_t)BB * HH];           // tf32-rounded x
__device__ __align__(256) float g_hall_tf[(size_t)(LL + 1) * BB * HH]; // tf32-rounded h_all
__device__ __align__(256) float g_h_tf[(size_t)BB * HH];           // tf32-rounded h (epilogue-written)

// ---------------- PTX helpers (arch-portable, sm_80+ baseline) ----------------
__device__ __forceinline__ uint32_t smem_u32(const void* p) {
    uint32_t a;
    asm("{ .reg .u64 t; cvta.to.shared.u64 t, %1; cvt.u32.u64 %0, t; }" : "=r"(a) : "l"(p));
    return a;
}
__device__ __forceinline__ void cp16(uint32_t s, const void* g) {
    asm volatile("cp.async.cg.shared.global [%0], [%1], 16;" :: "r"(s), "l"(g));
}
__device__ __forceinline__ uint32_t lds_u32(uint32_t addr) {
    uint32_t u; asm volatile("ld.shared.b32 %0, [%1];" : "=r"(u) : "r"(addr));
    return u;
}
__device__ __forceinline__ void mma1688(float c[4], const uint32_t a[4],
                                        uint32_t b0, uint32_t b1) {
    asm volatile("mma.sync.aligned.m16n8k8.row.col.f32.tf32.tf32.f32 "
        "{%0,%1,%2,%3}, {%4,%5,%6,%7}, {%8,%9}, {%0,%1,%2,%3};"
        : "+f"(c[0]), "+f"(c[1]), "+f"(c[2]), "+f"(c[3])
        : "r"(a[0]), "r"(a[1]), "r"(a[2]), "r"(a[3]), "r"(b0), "r"(b1));
}
__device__ __forceinline__ float rna_tf32(float x) {
    uint32_t u; asm("cvt.rna.tf32.f32 %0, %1;" : "=r"(u) : "f"(x));
    return __uint_as_float(u);
}
__device__ __forceinline__ float sigf(float x) {
    return __fdividef(1.0f, 1.0f + __expf(-x));
}
__device__ __forceinline__ float tanhfast(float x) {
    return __fdividef(2.0f, 1.0f + __expf(-2.0f * x)) - 1.0f;
}

// ---------------- tf32 TN GEMM via mma.sync, 3-stage cp.async, fused LSTM epilogue ----------------
// C[m,n] = sum_k A[m,k]*W[n,k] (+bias). A = [A1 | A2] along K (each [B,256] fp32, pre-rounded tf32).
// Tile 128x128, BK=32. Smem rows padded to 144B -> immediate-offset LDS, no XOR swizzle.
#define TM 128
#define TN 128
#define NTHREADS 256
#define ROWB 144                           // 128B data + 16B pad
#define STAGE_A (TM * ROWB)                // 18 KB
#define STAGE_B (TN * ROWB)                // 18 KB
#define STAGE   (STAGE_A + STAGE_B)        // 36 KB
#define NSTAGE  3
#define SMEMSZ  (NSTAGE * STAGE)           // 108 KB -> 2 CTAs/SM (216 KB)

template<bool FUSED>
__global__ void __launch_bounds__(NTHREADS, 2) mma_gemm(
    const float* __restrict__ A1, const float* __restrict__ A2,
    const float* __restrict__ B, int sB, int Ktot,
    const float* __restrict__ bias,
    float* __restrict__ C, int sC,
    const float* __restrict__ c_in, float* __restrict__ h_out, float* __restrict__ c_out,
    float* __restrict__ htf_out)
{
    extern __shared__ __align__(128) char dsm[];
    const int tid  = threadIdx.x;
    const int lane = tid & 31;
    const int wid  = tid >> 5;
    const int wm   = wid & 1;        // 2 warps along M (64 rows)
    const int wn   = wid >> 1;       // 4 warps along N (32 cols)
    const int m0   = blockIdx.y * TM;
    const int n0   = blockIdx.x * TN;
    const uint32_t sbase = smem_u32(dsm);

    const int niter = Ktot >> 5;     // BK = 32

    float c[4][4][4];
    #pragma unroll
    for (int i = 0; i < 4; ++i)
        #pragma unroll
        for (int j = 0; j < 4; ++j)
            #pragma unroll
            for (int q = 0; q < 4; ++q) c[i][j][q] = 0.0f;

    auto load_stage = [&](int buf, int it) {
        const int kc = it << 5;
        const uint32_t sa = sbase + buf * STAGE;
        const uint32_t sb = sa + STAGE_A;
        const float* Asrc; int koff;
        if (kc < 256) { Asrc = A1; koff = kc; } else { Asrc = A2; koff = kc - 256; }
        #pragma unroll
        for (int i = 0; i < 4; ++i) {                    // A: 128 rows x 8 chunks of 16B
            int idx = tid + i * NTHREADS;
            int row = idx >> 3, kg = idx & 7;
            cp16(sa + row * ROWB + (kg << 4),
                 Asrc + (size_t)(m0 + row) * 256 + koff + kg * 4);
        }
        #pragma unroll
        for (int i = 0; i < 4; ++i) {                    // B: 128 rows x 8 chunks
            int idx = tid + i * NTHREADS;
            int row = idx >> 3, kg = idx & 7;
            cp16(sb + row * ROWB + (kg << 4),
                 B + (size_t)(n0 + row) * sB + kc + kg * 4);
        }
        asm volatile("cp.async.commit_group;");
    };

    load_stage(0, 0);
    load_stage(1, 1);

    const int lr = lane >> 2;   // 0..7
    const int lc = lane & 3;    // k-low

    int buf = 0;
    #pragma unroll 1
    for (int i = 0; i < niter; ++i) {
        if (i + 2 < niter) {
            load_stage((buf + 2) % NSTAGE, i + 2);
            asm volatile("cp.async.wait_group 2;");
        } else {
            asm volatile("cp.async.wait_group 0;");
        }
        __syncthreads();

        const uint32_t sa = sbase + buf * STAGE;
        const uint32_t sb = sa + STAGE_A;
        // per-thread base addresses (immediate offsets handle ch/mi/nj/row+8)
        const uint32_t abase = sa + (wm * 64 + lr) * ROWB + lc * 4;
        const uint32_t bbase = sb + (wn * 32 + lr) * ROWB + lc * 4;

        #pragma unroll
        for (int ks = 0; ks < 4; ++ks) {                 // 4 k8 steps per BK=32
            const int o0 = ks * 32;                      // ch0 byte offset
            const int o1 = o0 + 16;                      // ch1
            uint32_t a[4][4];
            #pragma unroll
            for (int mi = 0; mi < 4; ++mi) {
                const uint32_t ab = abase + mi * (16 * ROWB);
                a[mi][0] = lds_u32(ab + o0);
                a[mi][1] = lds_u32(ab + 8 * ROWB + o0);
                a[mi][2] = lds_u32(ab + o1);
                a[mi][3] = lds_u32(ab + 8 * ROWB + o1);
            }
            uint32_t b[4][2];
            #pragma unroll
            for (int nj = 0; nj < 4; ++nj) {
                const uint32_t bb = bbase + nj * (8 * ROWB);
                b[nj][0] = lds_u32(bb + o0);
                b[nj][1] = lds_u32(bb + o1);
            }
            #pragma unroll
            for (int mi = 0; mi < 4; ++mi)
                #pragma unroll
                for (int nj = 0; nj < 4; ++nj)
                    mma1688(c[mi][nj], a[mi], b[nj][0], b[nj][1]);
        }
        __syncthreads();
        buf = (buf + 1 == NSTAGE) ? 0 : buf + 1;
    }

    if (!FUSED) {
        #pragma unroll
        for (int mi = 0; mi < 4; ++mi) {
            const int r0 = m0 + wm * 64 + mi * 16 + lr;
            #pragma unroll
            for (int nj = 0; nj < 4; ++nj) {
                const int col = n0 + wn * 32 + nj * 8 + lc * 2;
                float bx = 0.0f, by = 0.0f;
                if (bias) { bx = bias[col]; by = bias[col + 1]; }
                *(float2*)&C[(size_t)r0 * sC + col] =
                    make_float2(c[mi][nj][0] + bx, c[mi][nj][1] + by);
                *(float2*)&C[(size_t)(r0 + 8) * sC + col] =
                    make_float2(c[mi][nj][2] + bx, c[mi][nj][3] + by);
            }
        }
    } else {
        // fused LSTM epilogue. Gate-reordered columns: within each 32-col warp tile,
        // col = gate*8 + unit_local; thread's 4 col-groups (nj) = gates (i,f,g,o)
        // of units (lane&3)*2 and +1.
        const int ub = ((n0 + wn * 32) >> 2) + (lc << 1);   // global unit for e=0
        float bsv[4][2];
        #pragma unroll
        for (int g = 0; g < 4; ++g) {
            bsv[g][0] = bias[n0 + wn * 32 + g * 8 + lc * 2];
            bsv[g][1] = bias[n0 + wn * 32 + g * 8 + lc * 2 + 1];
        }
        #pragma unroll
        for (int mi = 0; mi < 4; ++mi) {
            #pragma unroll
            for (int rh = 0; rh < 2; ++rh) {
                const int row = m0 + wm * 64 + mi * 16 + rh * 8 + lr;
                const float2 cin = *(const float2*)&c_in[(size_t)row * HH + ub];
                float hv[2], cv[2];
                #pragma unroll
                for (int e = 0; e < 2; ++e) {
                    const int q = rh * 2 + e;
                    float gi = sigf    (c[mi][0][q] + bsv[0][e]);
                    float gf = sigf    (c[mi][1][q] + bsv[1][e]);
                    float gg = tanhfast(c[mi][2][q] + bsv[2][e]);
                    float go = sigf    (c[mi][3][q] + bsv[3][e]);
                    float ci = e ? cin.y : cin.x;
                    cv[e] = gf * ci + gi * gg;
                    hv[e] = go * tanhfast(cv[e]);
                }
                *(float2*)&c_out[(size_t)row * HH + ub] = make_float2(cv[0], cv[1]);
                *(float2*)&h_out[(size_t)row * HH + ub] = make_float2(hv[0], hv[1]);
                *(float2*)&htf_out[(size_t)row * HH + ub] =
                    make_float2(rna_tf32(hv[0]), rna_tf32(hv[1]));
            }
        }
    }
}

// ---------------- repack / rounding kernels (once per call) ----------------
__global__ void __launch_bounds__(256) conv_w(
    const float* __restrict__ Wih0, const float* __restrict__ Whh0,
    const float* __restrict__ Wih,  const float* __restrict__ Whh)
{
    int t  = blockIdx.x * blockDim.x + threadIdx.x;     // 1048576
    int k4 = (t & 127) << 2;
    int nn = (t >> 7) & 1023;
    int l  = t >> 17;
    int gate = (nn >> 3) & 3;
    int unit = ((nn >> 5) << 3) + (nn & 7);
    int no   = gate * 256 + unit;
    const float* src;
    if (l == 0) src = (k4 < 256) ? (Wih0 + (size_t)no * 256 + k4)
                                 : (Whh0 + (size_t)no * 256 + (k4 - 256));
    else        src = (k4 < 256) ? (Wih + ((size_t)(l - 1) * G4 + no) * 256 + k4)
                                 : (Whh + ((size_t)(l - 1) * G4 + no) * 256 + (k4 - 256));
    float4 v = *(const float4*)src;
    v.x = rna_tf32(v.x); v.y = rna_tf32(v.y); v.z = rna_tf32(v.z); v.w = rna_tf32(v.w);
    *(float4*)&g_w[((size_t)l * G4 + nn) * KT + k4] = v;
}

__global__ void __launch_bounds__(256) conv_wout(const float* __restrict__ Wout) {
    int t = blockIdx.x * blockDim.x + threadIdx.x;      // 16384
    int n = t >> 6, k4 = (t & 63) << 2;
    float4 v = *(const float4*)(Wout + (size_t)n * HH + k4);
    v.x = rna_tf32(v.x); v.y = rna_tf32(v.y); v.z = rna_tf32(v.z); v.w = rna_tf32(v.w);
    *(float4*)&g_wout[(size_t)n * HH + k4] = v;
}

__global__ void __launch_bounds__(256) conv_bias(
    const float* __restrict__ bih0, const float* __restrict__ bhh0,
    const float* __restrict__ bih,  const float* __restrict__ bhh)
{
    int t  = blockIdx.x * blockDim.x + threadIdx.x;     // 8192
    int nn = t & 1023;
    int l  = t >> 10;
    int gate = (nn >> 3) & 3;
    int unit = ((nn >> 5) << 3) + (nn & 7);
    int no   = gate * 256 + unit;
    float v;
    if (l == 0) v = bih0[no] + bhh0[no];
    else        v = bih[(size_t)(l - 1) * G4 + no] + bhh[(size_t)(l - 1) * G4 + no];
    g_bias[t] = v;
}

// round x and all h_all slabs to tf32 (dst = g_x_tf ++ g_hall_tf handled by two launches)
__global__ void __launch_bounds__(256) round_tf(const float* __restrict__ src, float* __restrict__ dst) {
    size_t t = (size_t)blockIdx.x * blockDim.x + threadIdx.x;   // float4 index
    float4 v = *(const float4*)(src + t * 4);
    v.x = rna_tf32(v.x); v.y = rna_tf32(v.y); v.z = rna_tf32(v.z); v.w = rna_tf32(v.w);
    *(float4*)(dst + t * 4) = v;
}

// ---------------- launch ----------------
extern "C" void kernel_launch(void* const* d_in, const int* in_sizes, int n_in,
                              void* d_out, int out_size)
{
    const float* x     = (const float*)d_in[0];
    const float* h_all = (const float*)d_in[1];
    const float* c_all = (const float*)d_in[2];
    const float* Wih0  = (const float*)d_in[3];
    const float* Whh0  = (const float*)d_in[4];
    const float* bih0  = (const float*)d_in[5];
    const float* bhh0  = (const float*)d_in[6];
    const float* Wih   = (const float*)d_in[7];
    const float* Whh   = (const float*)d_in[8];
    const float* bih   = (const float*)d_in[9];
    const float* bhh   = (const float*)d_in[10];
    const float* Wout  = (const float*)d_in[11];
    const float* bout  = (const float*)d_in[12];

    float* out = (float*)d_out;
    float* hs  = out + (size_t)BB * OUTF;
    float* cs  = hs + (size_t)(LL + 1) * BB * HH;

    float *w, *wout, *biasc, *xtf, *halltf, *htf;
    cudaGetSymbolAddress((void**)&w,      g_w);
    cudaGetSymbolAddress((void**)&wout,   g_wout);
    cudaGetSymbolAddress((void**)&biasc,  g_bias);
    cudaGetSymbolAddress((void**)&xtf,    g_x_tf);
    cudaGetSymbolAddress((void**)&halltf, g_hall_tf);
    cudaGetSymbolAddress((void**)&htf,    g_h_tf);

    cudaFuncSetAttribute(mma_gemm<true>,  cudaFuncAttributeMaxDynamicSharedMemorySize, SMEMSZ);
    cudaFuncSetAttribute(mma_gemm<false>, cudaFuncAttributeMaxDynamicSharedMemorySize, SMEMSZ);

    conv_w<<<4096, 256>>>(Wih0, Whh0, Wih, Whh);
    conv_wout<<<64, 256>>>(Wout);
    conv_bias<<<32, 256>>>(bih0, bhh0, bih, bhh);
    round_tf<<<(BB * HH / 4) / 256, 256>>>(x, xtf);
    round_tf<<<((LL + 1) * BB * HH / 4) / 256, 256>>>(h_all, halltf);

    for (int l = 0; l <= LL; ++l) {
        const float* a1 = (l == 0) ? xtf : htf;
        mma_gemm<true><<<dim3(G4 / TN, BB / TM), NTHREADS, SMEMSZ>>>(
            a1, halltf + (size_t)l * BB * HH,
            w + (size_t)l * G4 * KT, KT, KT,
            biasc + (size_t)l * G4,
            nullptr, 0,
            c_all + (size_t)l * BB * HH,
            hs + (size_t)l * BB * HH, cs + (size_t)l * BB * HH,
            htf);
    }

    // output = h_last @ Wout.T + bout
    mma_gemm<false><<<dim3(OUTF / TN, BB / TM), NTHREADS, SMEMSZ>>>(
        htf, nullptr,
        wout, HH, HH,
        bout, out, OUTF,
        nullptr, nullptr, nullptr, nullptr);
}